// round 8
// baseline (speedup 1.0000x reference)
#include <cuda_runtime.h>
#include <cuda_bf16.h>
#include <cstdint>

// ---------------------------------------------------------------------------
// ShapletLearner via bf16 mma.sync m16n8k16, 2-term split (hi+lo), 3 passes.
// R8: minimize non-HMMA issue slots:
//   - B pre-scaled by -2 (exact in bf16) so accumulator directly = -2*cross
//   - first MMA of each chain takes C = {wq0,wq0,wq1,wq1} (wsq folded in)
//   - merge per tile = 8 FMNMX only
//   - hi/lo ts pairs interleaved in one uint2 array -> 2 LDS.64 refills/tile
// ---------------------------------------------------------------------------

constexpr int Bc = 2048;
constexpr int Qc = 1024;
constexpr int Kc = 32;
constexpr int Lc = 64;
constexpr int Sc = Qc - Kc + 1;   // 993

// D += A*B
#define MMAB(d0,d1,d2,d3, a0,a1,a2,a3, b0,b1) \
    asm("mma.sync.aligned.m16n8k16.row.col.f32.bf16.bf16.f32 " \
        "{%0,%1,%2,%3}, {%4,%5,%6,%7}, {%8,%9}, {%0,%1,%2,%3};" \
        : "+f"(d0), "+f"(d1), "+f"(d2), "+f"(d3) \
        : "r"(a0), "r"(a1), "r"(a2), "r"(a3), "r"(b0), "r"(b1))

// D = A*B + {c0,c0,c1,c1}  (wsq folded into fresh accumulator chain)
#define MMAC(d0,d1,d2,d3, a0,a1,a2,a3, b0,b1, c0,c1) \
    asm("mma.sync.aligned.m16n8k16.row.col.f32.bf16.bf16.f32 " \
        "{%0,%1,%2,%3}, {%4,%5,%6,%7}, {%8,%9}, {%10,%11,%12,%13};" \
        : "=f"(d0), "=f"(d1), "=f"(d2), "=f"(d3) \
        : "r"(a0), "r"(a1), "r"(a2), "r"(a3), "r"(b0), "r"(b1), \
          "f"(c0), "f"(c0), "f"(c1), "f"(c1))

// one m16 tile: ring offset O = (2*TT)%6 (compile-time), tile index TT
// acc = wq - 2*(ah*bh + ah*bl + al*bh); then mn = min(mn, acc)
#define TILE(O, TT) do { \
    enum { I0 = (O) % 6, I1 = ((O) + 1) % 6, I2 = ((O) + 2) % 6, \
           I3 = ((O) + 3) % 6, I4 = ((O) + 4) % 6, \
           S5 = ((O) + 5) % 6, S6 = (O) % 6 }; \
    const int s0_ = (TT) << 4; \
    const float wq0_ = wsq_sh[s0_ + nrow]; \
    const float wq1_ = wsq_sh[s0_ + nrow + 8]; \
    float d00,d01,d02,d03,d10,d11,d12,d13; \
    MMAC(d00,d01,d02,d03, rh[I0],rh[I1],rh[I1],rh[I2], Bh[0][0][0],Bh[0][0][1], wq0_, wq1_); \
    MMAC(d10,d11,d12,d13, rh[I0],rh[I1],rh[I1],rh[I2], Bh[1][0][0],Bh[1][0][1], wq0_, wq1_); \
    MMAB(d00,d01,d02,d03, rh[I0],rh[I1],rh[I1],rh[I2], Bl[0][0][0],Bl[0][0][1]); \
    MMAB(d10,d11,d12,d13, rh[I0],rh[I1],rh[I1],rh[I2], Bl[1][0][0],Bl[1][0][1]); \
    MMAB(d00,d01,d02,d03, rl[I0],rl[I1],rl[I1],rl[I2], Bh[0][0][0],Bh[0][0][1]); \
    MMAB(d10,d11,d12,d13, rl[I0],rl[I1],rl[I1],rl[I2], Bh[1][0][0],Bh[1][0][1]); \
    MMAB(d00,d01,d02,d03, rh[I2],rh[I3],rh[I3],rh[I4], Bh[0][1][0],Bh[0][1][1]); \
    MMAB(d10,d11,d12,d13, rh[I2],rh[I3],rh[I3],rh[I4], Bh[1][1][0],Bh[1][1][1]); \
    MMAB(d00,d01,d02,d03, rh[I2],rh[I3],rh[I3],rh[I4], Bl[0][1][0],Bl[0][1][1]); \
    MMAB(d10,d11,d12,d13, rh[I2],rh[I3],rh[I3],rh[I4], Bl[1][1][0],Bl[1][1][1]); \
    MMAB(d00,d01,d02,d03, rl[I2],rl[I3],rl[I3],rl[I4], Bh[0][1][0],Bh[0][1][1]); \
    MMAB(d10,d11,d12,d13, rl[I2],rl[I3],rl[I3],rl[I4], Bh[1][1][0],Bh[1][1][1]); \
    mn00 = fminf(mn00, d00);  mn01 = fminf(mn01, d01); \
    mn02 = fminf(mn02, d02);  mn03 = fminf(mn03, d03); \
    mn10 = fminf(mn10, d10);  mn11 = fminf(mn11, d11); \
    mn12 = fminf(mn12, d12);  mn13 = fminf(mn13, d13); \
    { const int gi_ = s0_ + tb; \
      const uint2 p5 = hl_sh[gi_ + 40]; \
      const uint2 p6 = hl_sh[gi_ + 48]; \
      rh[S5] = p5.x;  rl[S5] = p5.y; \
      rh[S6] = p6.x;  rl[S6] = p6.y; } \
} while (0)

static __device__ __forceinline__ uint32_t pack_bf16x2(float lo, float hi) {
    uint32_t r;
    asm("cvt.rn.bf16x2.f32 %0, %1, %2;" : "=r"(r) : "f"(hi), "f"(lo));
    return r;
}

__global__ __launch_bounds__(128) void shapelet_bmma(
    const float* __restrict__ ts,        // [B, Q]
    const float* __restrict__ shp,       // [L, K]
    const float* __restrict__ fc_w,      // [2, L]
    const float* __restrict__ fc_b,      // [2]
    float* __restrict__ out)             // [B, 2]
{
    __shared__ __align__(16) float ts_sh[1152];   // fp32, zero-padded
    __shared__ __align__(16) uint2 hl_sh[1120];   // {bf16 pair hi, bf16 pair lo}
    __shared__ __align__(16) float wsq_sh[1056];  // 1e38 guard for s >= Sc
    __shared__ float ssq_sh[Lc];
    __shared__ float dsh[Lc];

    const int b    = blockIdx.x;
    const int tid  = threadIdx.x;
    const int w    = tid >> 5;
    const int lane = tid & 31;
    const int nrow = lane >> 2;
    const int kq   = lane & 3;

    // ---- stage ts + zero pad to 1152 ----
    {
        const float4* src = reinterpret_cast<const float4*>(ts + (size_t)b * Qc);
        float4* dst = reinterpret_cast<float4*>(ts_sh);
        dst[tid]       = src[tid];
        dst[128 + tid] = src[128 + tid];
        if (tid < 32) dst[256 + tid] = make_float4(0.f, 0.f, 0.f, 0.f);
    }
    __syncthreads();

    // ---- interleaved bf16 hi/lo pair array ----
    #pragma unroll
    for (int i = tid; i < 1120; i += 128) {
        const float x0 = ts_sh[i], x1 = ts_sh[i + 1];
        const __nv_bfloat16 h0 = __float2bfloat16_rn(x0);
        const __nv_bfloat16 h1 = __float2bfloat16_rn(x1);
        const uint32_t hi = (uint32_t)__bfloat16_as_ushort(h0)
                          | ((uint32_t)__bfloat16_as_ushort(h1) << 16);
        const uint32_t lo = pack_bf16x2(x0 - __bfloat162float(h0),
                                        x1 - __bfloat162float(h1));
        hl_sh[i] = make_uint2(hi, lo);
    }

    // ---- wsq[s] exact fp32 (incremental, 9 windows / thread) ----
    {
        const int sbase = tid * 9;
        if (sbase < 1056) {
            float ww = 0.f;
            #pragma unroll
            for (int k = 0; k < Kc; k++) {
                const float x = ts_sh[sbase + k];
                ww = fmaf(x, x, ww);
            }
            wsq_sh[sbase] = (sbase < Sc) ? ww : 1e38f;
            #pragma unroll
            for (int i = 1; i < 9; i++) {
                const int s = sbase + i;
                const float xo = ts_sh[s - 1], xn = ts_sh[s + 31];
                ww = ww - xo * xo + xn * xn;
                if (s < 1056) wsq_sh[s] = (s < Sc) ? ww : 1e38f;
            }
        }
    }

    // ---- ssq[l] exact fp32 ----
    if (tid < Lc) {
        float s = 0.f;
        #pragma unroll
        for (int k = 0; k < Kc; k++) {
            const float v = shp[tid * Kc + k];
            s = fmaf(v, v, s);
        }
        ssq_sh[tid] = s;
    }

    // ---- B fragments (hi/lo) from -2*shp: warp covers n = w*16..w*16+15 ----
    uint32_t Bh[2][2][2], Bl[2][2][2];
    #pragma unroll
    for (int nt = 0; nt < 2; nt++)
        #pragma unroll
        for (int kc = 0; kc < 2; kc++)
            #pragma unroll
            for (int j = 0; j < 2; j++) {
                const int n = w * 16 + nt * 8 + nrow;
                const int k = 16 * kc + 8 * j + 2 * kq;
                const float x0 = -2.0f * shp[n * Kc + k];
                const float x1 = -2.0f * shp[n * Kc + k + 1];
                const __nv_bfloat16 h0 = __float2bfloat16_rn(x0);
                const __nv_bfloat16 h1 = __float2bfloat16_rn(x1);
                Bh[nt][kc][j] = (uint32_t)__bfloat16_as_ushort(h0)
                              | ((uint32_t)__bfloat16_as_ushort(h1) << 16);
                Bl[nt][kc][j] = pack_bf16x2(x0 - __bfloat162float(h0),
                                            x1 - __bfloat162float(h1));
            }
    __syncthreads();

    // ---- main loop: 66 m16 tiles, 6-slot pair ring ----
    float mn00 = 3.4e38f, mn01 = 3.4e38f, mn02 = 3.4e38f, mn03 = 3.4e38f;
    float mn10 = 3.4e38f, mn11 = 3.4e38f, mn12 = 3.4e38f, mn13 = 3.4e38f;

    const int tb = nrow + 2 * kq;   // in [0,13]
    uint32_t rh[6], rl[6];
    #pragma unroll
    for (int m = 0; m < 5; m++) {
        const uint2 p = hl_sh[tb + 8 * m];
        rh[m] = p.x;  rl[m] = p.y;
    }
    rh[5] = 0u; rl[5] = 0u;

    #pragma unroll 1
    for (int it = 0; it < 11; it++) {
        const int t6 = it * 6;
        TILE(0, t6);
        TILE(2, t6 + 1);
        TILE(4, t6 + 2);
        TILE(0, t6 + 3);
        TILE(2, t6 + 4);
        TILE(4, t6 + 5);
    }

    // ---- reduce rows in-thread, then across row groups via shfl ----
    float m0 = fminf(mn00, mn02);
    float m1 = fminf(mn01, mn03);
    float m2 = fminf(mn10, mn12);
    float m3 = fminf(mn11, mn13);
    #pragma unroll
    for (int off = 4; off < 32; off <<= 1) {
        m0 = fminf(m0, __shfl_xor_sync(0xffffffffu, m0, off));
        m1 = fminf(m1, __shfl_xor_sync(0xffffffffu, m1, off));
        m2 = fminf(m2, __shfl_xor_sync(0xffffffffu, m2, off));
        m3 = fminf(m3, __shfl_xor_sync(0xffffffffu, m3, off));
    }
    if (nrow == 0) {
        const int n0 = w * 16 + 2 * kq;
        dsh[n0]     = (m0 + ssq_sh[n0])     * (1.0f / Kc);
        dsh[n0 + 1] = (m1 + ssq_sh[n0 + 1]) * (1.0f / Kc);
        dsh[n0 + 8] = (m2 + ssq_sh[n0 + 8]) * (1.0f / Kc);
        dsh[n0 + 9] = (m3 + ssq_sh[n0 + 9]) * (1.0f / Kc);
    }
    __syncthreads();

    // ---- FC epilogue ----
    if (tid < 2 * 32) {
        const int c = tid >> 5;
        const int l = tid & 31;
        float p = dsh[l] * fc_w[c * Lc + l]
                + dsh[l + 32] * fc_w[c * Lc + l + 32];
        #pragma unroll
        for (int off = 16; off > 0; off >>= 1)
            p += __shfl_down_sync(0xffffffffu, p, off);
        if (l == 0) out[b * 2 + c] = p + fc_b[c];
    }
}

extern "C" void kernel_launch(void* const* d_in, const int* in_sizes, int n_in,
                              void* d_out, int out_size)
{
    (void)in_sizes; (void)n_in; (void)out_size;
    const float* ts   = (const float*)d_in[0];
    const float* shp  = (const float*)d_in[1];
    const float* fc_w = (const float*)d_in[2];
    const float* fc_b = (const float*)d_in[3];
    float* out        = (float*)d_out;
    shapelet_bmma<<<Bc, 128>>>(ts, shp, fc_w, fc_b, out);
}

// round 9
// speedup vs baseline: 1.5558x; 1.5558x over previous
#include <cuda_runtime.h>
#include <cuda_bf16.h>
#include <cstdint>

// ---------------------------------------------------------------------------
// ShapletLearner via bf16 mma.sync m16n8k16, 2-term split (hi+lo), 3 passes.
// R9 = R5 + software-pipelined merge: two accumulator sets (A/B); tile t's
// merge (8 FFMA + 8 FMNMX) is deferred until after tile t+1's 12 HMMAs are
// issued, hiding HMMA result latency. MMAZ zero-init kills 8 MOVs/tile.
// ---------------------------------------------------------------------------

constexpr int Bc = 2048;
constexpr int Qc = 1024;
constexpr int Kc = 32;
constexpr int Lc = 64;
constexpr int Sc = Qc - Kc + 1;   // 993

// D += A*B
#define MMAB(d0,d1,d2,d3, a0,a1,a2,a3, b0,b1) \
    asm("mma.sync.aligned.m16n8k16.row.col.f32.bf16.bf16.f32 " \
        "{%0,%1,%2,%3}, {%4,%5,%6,%7}, {%8,%9}, {%0,%1,%2,%3};" \
        : "+f"(d0), "+f"(d1), "+f"(d2), "+f"(d3) \
        : "r"(a0), "r"(a1), "r"(a2), "r"(a3), "r"(b0), "r"(b1))

// D = A*B (C = 0, fresh chain, no zero-MOVs)
#define MMAZ(d0,d1,d2,d3, a0,a1,a2,a3, b0,b1) \
    asm("mma.sync.aligned.m16n8k16.row.col.f32.bf16.bf16.f32 " \
        "{%0,%1,%2,%3}, {%4,%5,%6,%7}, {%8,%9}, {%10,%11,%12,%13};" \
        : "=f"(d0), "=f"(d1), "=f"(d2), "=f"(d3) \
        : "r"(a0), "r"(a1), "r"(a2), "r"(a3), "r"(b0), "r"(b1), \
          "f"(0.f), "f"(0.f), "f"(0.f), "f"(0.f))

// Issue 12 HMMAs of one m16 tile into accumulator set S (dS0..dS7).
// Ring offset O = (2*TT)%6 compile-time. Also loads wq into wq0S/wq1S and
// refills ring slots for tile TT+1 at the end.
#define TILE_MMA(O, S, TT) do { \
    enum { I0 = (O) % 6, I1 = ((O) + 1) % 6, I2 = ((O) + 2) % 6, \
           I3 = ((O) + 3) % 6, I4 = ((O) + 4) % 6, S5 = ((O) + 5) % 6 }; \
    const int s0_ = (TT) << 4; \
    wq0##S = wsq_sh[s0_ + nrow]; \
    wq1##S = wsq_sh[s0_ + nrow + 8]; \
    MMAZ(d##S##0,d##S##1,d##S##2,d##S##3, rh[I0],rh[I1],rh[I1],rh[I2], Bh[0][0][0],Bh[0][0][1]); \
    MMAZ(d##S##4,d##S##5,d##S##6,d##S##7, rh[I0],rh[I1],rh[I1],rh[I2], Bh[1][0][0],Bh[1][0][1]); \
    MMAB(d##S##0,d##S##1,d##S##2,d##S##3, rh[I0],rh[I1],rh[I1],rh[I2], Bl[0][0][0],Bl[0][0][1]); \
    MMAB(d##S##4,d##S##5,d##S##6,d##S##7, rh[I0],rh[I1],rh[I1],rh[I2], Bl[1][0][0],Bl[1][0][1]); \
    MMAB(d##S##0,d##S##1,d##S##2,d##S##3, rl[I0],rl[I1],rl[I1],rl[I2], Bh[0][0][0],Bh[0][0][1]); \
    MMAB(d##S##4,d##S##5,d##S##6,d##S##7, rl[I0],rl[I1],rl[I1],rl[I2], Bh[1][0][0],Bh[1][0][1]); \
    MMAB(d##S##0,d##S##1,d##S##2,d##S##3, rh[I2],rh[I3],rh[I3],rh[I4], Bh[0][1][0],Bh[0][1][1]); \
    MMAB(d##S##4,d##S##5,d##S##6,d##S##7, rh[I2],rh[I3],rh[I3],rh[I4], Bh[1][1][0],Bh[1][1][1]); \
    MMAB(d##S##0,d##S##1,d##S##2,d##S##3, rh[I2],rh[I3],rh[I3],rh[I4], Bl[0][1][0],Bl[0][1][1]); \
    MMAB(d##S##4,d##S##5,d##S##6,d##S##7, rh[I2],rh[I3],rh[I3],rh[I4], Bl[1][1][0],Bl[1][1][1]); \
    MMAB(d##S##0,d##S##1,d##S##2,d##S##3, rl[I2],rl[I3],rl[I3],rl[I4], Bh[0][1][0],Bh[0][1][1]); \
    MMAB(d##S##4,d##S##5,d##S##6,d##S##7, rl[I2],rl[I3],rl[I3],rl[I4], Bh[1][1][0],Bh[1][1][1]); \
    { const int gi_ = s0_ + tb; \
      rh[S5] = pair_hi[gi_ + 40];  rl[S5] = pair_lo[gi_ + 40]; \
      rh[I0] = pair_hi[gi_ + 48];  rl[I0] = pair_lo[gi_ + 48]; } \
} while (0)

// merge set S into running mins (deferred one tile)
#define MERGE_S(S) do { \
    mn00 = fminf(mn00, fmaf(d##S##0, -2.f, wq0##S)); \
    mn01 = fminf(mn01, fmaf(d##S##1, -2.f, wq0##S)); \
    mn02 = fminf(mn02, fmaf(d##S##2, -2.f, wq1##S)); \
    mn03 = fminf(mn03, fmaf(d##S##3, -2.f, wq1##S)); \
    mn10 = fminf(mn10, fmaf(d##S##4, -2.f, wq0##S)); \
    mn11 = fminf(mn11, fmaf(d##S##5, -2.f, wq0##S)); \
    mn12 = fminf(mn12, fmaf(d##S##6, -2.f, wq1##S)); \
    mn13 = fminf(mn13, fmaf(d##S##7, -2.f, wq1##S)); \
} while (0)

static __device__ __forceinline__ uint32_t pack_bf16x2(float lo, float hi) {
    uint32_t r;
    asm("cvt.rn.bf16x2.f32 %0, %1, %2;" : "=r"(r) : "f"(hi), "f"(lo));
    return r;
}

__global__ __launch_bounds__(128) void shapelet_bmma(
    const float* __restrict__ ts,        // [B, Q]
    const float* __restrict__ shp,       // [L, K]
    const float* __restrict__ fc_w,      // [2, L]
    const float* __restrict__ fc_b,      // [2]
    float* __restrict__ out)             // [B, 2]
{
    __shared__ __align__(16) float    ts_sh[1152];    // fp32, zero-padded
    __shared__ __align__(16) uint32_t pair_hi[1120];  // (bf16 ts[i], ts[i+1])
    __shared__ __align__(16) uint32_t pair_lo[1120];  // residual pairs
    __shared__ __align__(16) float wsq_sh[1056];      // 1e38 guard s >= Sc
    __shared__ float ssq_sh[Lc];
    __shared__ float dsh[Lc];

    const int b    = blockIdx.x;
    const int tid  = threadIdx.x;
    const int w    = tid >> 5;
    const int lane = tid & 31;
    const int nrow = lane >> 2;
    const int kq   = lane & 3;

    // ---- stage ts + zero pad to 1152 ----
    {
        const float4* src = reinterpret_cast<const float4*>(ts + (size_t)b * Qc);
        float4* dst = reinterpret_cast<float4*>(ts_sh);
        dst[tid]       = src[tid];
        dst[128 + tid] = src[128 + tid];
        if (tid < 32) dst[256 + tid] = make_float4(0.f, 0.f, 0.f, 0.f);
    }
    __syncthreads();

    // ---- packed bf16 hi/lo pair arrays ----
    #pragma unroll
    for (int i = tid; i < 1120; i += 128) {
        const float x0 = ts_sh[i], x1 = ts_sh[i + 1];
        const __nv_bfloat16 h0 = __float2bfloat16_rn(x0);
        const __nv_bfloat16 h1 = __float2bfloat16_rn(x1);
        pair_hi[i] = (uint32_t)__bfloat16_as_ushort(h0)
                   | ((uint32_t)__bfloat16_as_ushort(h1) << 16);
        pair_lo[i] = pack_bf16x2(x0 - __bfloat162float(h0),
                                 x1 - __bfloat162float(h1));
    }

    // ---- wsq[s] exact fp32 (incremental, 9 windows / thread) ----
    {
        const int sbase = tid * 9;
        if (sbase < 1056) {
            float ww = 0.f;
            #pragma unroll
            for (int k = 0; k < Kc; k++) {
                const float x = ts_sh[sbase + k];
                ww = fmaf(x, x, ww);
            }
            wsq_sh[sbase] = (sbase < Sc) ? ww : 1e38f;
            #pragma unroll
            for (int i = 1; i < 9; i++) {
                const int s = sbase + i;
                const float xo = ts_sh[s - 1], xn = ts_sh[s + 31];
                ww = ww - xo * xo + xn * xn;
                if (s < 1056) wsq_sh[s] = (s < Sc) ? ww : 1e38f;
            }
        }
    }

    // ---- ssq[l] exact fp32 ----
    if (tid < Lc) {
        float s = 0.f;
        #pragma unroll
        for (int k = 0; k < Kc; k++) {
            const float v = shp[tid * Kc + k];
            s = fmaf(v, v, s);
        }
        ssq_sh[tid] = s;
    }

    // ---- B fragments (hi/lo): warp covers n = w*16 .. w*16+15 ----
    uint32_t Bh[2][2][2], Bl[2][2][2];
    #pragma unroll
    for (int nt = 0; nt < 2; nt++)
        #pragma unroll
        for (int kc = 0; kc < 2; kc++)
            #pragma unroll
            for (int j = 0; j < 2; j++) {
                const int n = w * 16 + nt * 8 + nrow;
                const int k = 16 * kc + 8 * j + 2 * kq;
                const float x0 = shp[n * Kc + k];
                const float x1 = shp[n * Kc + k + 1];
                const __nv_bfloat16 h0 = __float2bfloat16_rn(x0);
                const __nv_bfloat16 h1 = __float2bfloat16_rn(x1);
                Bh[nt][kc][j] = (uint32_t)__bfloat16_as_ushort(h0)
                              | ((uint32_t)__bfloat16_as_ushort(h1) << 16);
                Bl[nt][kc][j] = pack_bf16x2(x0 - __bfloat162float(h0),
                                            x1 - __bfloat162float(h1));
            }
    __syncthreads();

    // ---- main loop: 66 m16 tiles, 6-slot pair ring, pipelined merge ----
    float mn00 = 3.4e38f, mn01 = 3.4e38f, mn02 = 3.4e38f, mn03 = 3.4e38f;
    float mn10 = 3.4e38f, mn11 = 3.4e38f, mn12 = 3.4e38f, mn13 = 3.4e38f;

    const int tb = nrow + 2 * kq;   // in [0,13]
    uint32_t rh[6], rl[6];
    #pragma unroll
    for (int m = 0; m < 5; m++) {
        rh[m] = pair_hi[tb + 8 * m];
        rl[m] = pair_lo[tb + 8 * m];
    }
    rh[5] = 0u; rl[5] = 0u;

    float dA0,dA1,dA2,dA3,dA4,dA5,dA6,dA7;
    float dB0,dB1,dB2,dB3,dB4,dB5,dB6,dB7;
    float wq0A, wq1A, wq0B, wq1B;

    #pragma unroll 1
    for (int it = 0; it < 11; it++) {
        const int t6 = it * 6;
        TILE_MMA(0, A, t6);
        TILE_MMA(2, B, t6 + 1);
        MERGE_S(A);
        TILE_MMA(4, A, t6 + 2);
        MERGE_S(B);
        TILE_MMA(0, B, t6 + 3);
        MERGE_S(A);
        TILE_MMA(2, A, t6 + 4);
        MERGE_S(B);
        TILE_MMA(4, B, t6 + 5);
        MERGE_S(A);
        MERGE_S(B);
    }

    // ---- reduce rows in-thread, then across row groups via shfl ----
    float m0 = fminf(mn00, mn02);
    float m1 = fminf(mn01, mn03);
    float m2 = fminf(mn10, mn12);
    float m3 = fminf(mn11, mn13);
    #pragma unroll
    for (int off = 4; off < 32; off <<= 1) {
        m0 = fminf(m0, __shfl_xor_sync(0xffffffffu, m0, off));
        m1 = fminf(m1, __shfl_xor_sync(0xffffffffu, m1, off));
        m2 = fminf(m2, __shfl_xor_sync(0xffffffffu, m2, off));
        m3 = fminf(m3, __shfl_xor_sync(0xffffffffu, m3, off));
    }
    if (nrow == 0) {
        const int n0 = w * 16 + 2 * kq;
        dsh[n0]     = (m0 + ssq_sh[n0])     * (1.0f / Kc);
        dsh[n0 + 1] = (m1 + ssq_sh[n0 + 1]) * (1.0f / Kc);
        dsh[n0 + 8] = (m2 + ssq_sh[n0 + 8]) * (1.0f / Kc);
        dsh[n0 + 9] = (m3 + ssq_sh[n0 + 9]) * (1.0f / Kc);
    }
    __syncthreads();

    // ---- FC epilogue ----
    if (tid < 2 * 32) {
        const int c = tid >> 5;
        const int l = tid & 31;
        float p = dsh[l] * fc_w[c * Lc + l]
                + dsh[l + 32] * fc_w[c * Lc + l + 32];
        #pragma unroll
        for (int off = 16; off > 0; off >>= 1)
            p += __shfl_down_sync(0xffffffffu, p, off);
        if (l == 0) out[b * 2 + c] = p + fc_b[c];
    }
}

extern "C" void kernel_launch(void* const* d_in, const int* in_sizes, int n_in,
                              void* d_out, int out_size)
{
    (void)in_sizes; (void)n_in; (void)out_size;
    const float* ts   = (const float*)d_in[0];
    const float* shp  = (const float*)d_in[1];
    const float* fc_w = (const float*)d_in[2];
    const float* fc_b = (const float*)d_in[3];
    float* out        = (float*)d_out;
    shapelet_bmma<<<Bc, 128>>>(ts, shp, fc_w, fc_b, out);
}

// round 10
// speedup vs baseline: 2.6549x; 1.7064x over previous
#include <cuda_runtime.h>
#include <cuda_fp16.h>
#include <cstdint>

// ---------------------------------------------------------------------------
// ShapletLearner via single-pass fp16 mma.sync m16n8k16:
//   cross = Hankel(ts) @ shp^T in fp16 (quantization err ~2e-3 abs on raw
//   dist ~64 -> ~1e-4 final rel err; wsq/ssq exact fp32).
//   dist = (wsq - 2*cross + ssq)/K ; d[l]=min_s ; out = d@W^T + b
// R10 = R9 pipeline (A/B accumulator sets, deferred merge) with 4 HMMA/tile
// (was 12): legacy HMMA pipe is the hard ceiling, so cut instruction count.
// ---------------------------------------------------------------------------

constexpr int Bc = 2048;
constexpr int Qc = 1024;
constexpr int Kc = 32;
constexpr int Lc = 64;
constexpr int Sc = Qc - Kc + 1;   // 993

// D += A*B (fp16 in, fp32 accum)
#define MMAB(d0,d1,d2,d3, a0,a1,a2,a3, b0,b1) \
    asm("mma.sync.aligned.m16n8k16.row.col.f32.f16.f16.f32 " \
        "{%0,%1,%2,%3}, {%4,%5,%6,%7}, {%8,%9}, {%0,%1,%2,%3};" \
        : "+f"(d0), "+f"(d1), "+f"(d2), "+f"(d3) \
        : "r"(a0), "r"(a1), "r"(a2), "r"(a3), "r"(b0), "r"(b1))

// D = A*B (C = 0)
#define MMAZ(d0,d1,d2,d3, a0,a1,a2,a3, b0,b1) \
    asm("mma.sync.aligned.m16n8k16.row.col.f32.f16.f16.f32 " \
        "{%0,%1,%2,%3}, {%4,%5,%6,%7}, {%8,%9}, {%10,%11,%12,%13};" \
        : "=f"(d0), "=f"(d1), "=f"(d2), "=f"(d3) \
        : "r"(a0), "r"(a1), "r"(a2), "r"(a3), "r"(b0), "r"(b1), \
          "f"(0.f), "f"(0.f), "f"(0.f), "f"(0.f))

// Issue 4 HMMAs of one m16 tile into accumulator set S (dS0..dS7),
// load wq0S/wq1S, refill ring slots for the next tile.
#define TILE_MMA(O, S, TT) do { \
    enum { I0 = (O) % 6, I1 = ((O) + 1) % 6, I2 = ((O) + 2) % 6, \
           I3 = ((O) + 3) % 6, I4 = ((O) + 4) % 6, S5 = ((O) + 5) % 6 }; \
    const int s0_ = (TT) << 4; \
    wq0##S = wsq_sh[s0_ + nrow]; \
    wq1##S = wsq_sh[s0_ + nrow + 8]; \
    MMAZ(d##S##0,d##S##1,d##S##2,d##S##3, rr[I0],rr[I1],rr[I1],rr[I2], Bf[0][0][0],Bf[0][0][1]); \
    MMAZ(d##S##4,d##S##5,d##S##6,d##S##7, rr[I0],rr[I1],rr[I1],rr[I2], Bf[1][0][0],Bf[1][0][1]); \
    MMAB(d##S##0,d##S##1,d##S##2,d##S##3, rr[I2],rr[I3],rr[I3],rr[I4], Bf[0][1][0],Bf[0][1][1]); \
    MMAB(d##S##4,d##S##5,d##S##6,d##S##7, rr[I2],rr[I3],rr[I3],rr[I4], Bf[1][1][0],Bf[1][1][1]); \
    { const int gi_ = s0_ + tb; \
      rr[S5] = pair16[gi_ + 40]; \
      rr[I0] = pair16[gi_ + 48]; } \
} while (0)

// merge set S into running mins (deferred one tile)
#define MERGE_S(S) do { \
    mn00 = fminf(mn00, fmaf(d##S##0, -2.f, wq0##S)); \
    mn01 = fminf(mn01, fmaf(d##S##1, -2.f, wq0##S)); \
    mn02 = fminf(mn02, fmaf(d##S##2, -2.f, wq1##S)); \
    mn03 = fminf(mn03, fmaf(d##S##3, -2.f, wq1##S)); \
    mn10 = fminf(mn10, fmaf(d##S##4, -2.f, wq0##S)); \
    mn11 = fminf(mn11, fmaf(d##S##5, -2.f, wq0##S)); \
    mn12 = fminf(mn12, fmaf(d##S##6, -2.f, wq1##S)); \
    mn13 = fminf(mn13, fmaf(d##S##7, -2.f, wq1##S)); \
} while (0)

static __device__ __forceinline__ uint32_t pack_f16x2(float lo, float hi) {
    uint32_t r;
    asm("cvt.rn.f16x2.f32 %0, %1, %2;" : "=r"(r) : "f"(hi), "f"(lo));
    return r;
}

__global__ __launch_bounds__(128) void shapelet_hmma(
    const float* __restrict__ ts,        // [B, Q]
    const float* __restrict__ shp,       // [L, K]
    const float* __restrict__ fc_w,      // [2, L]
    const float* __restrict__ fc_b,      // [2]
    float* __restrict__ out)             // [B, 2]
{
    __shared__ __align__(16) float    ts_sh[1152];   // fp32, zero-padded
    __shared__ __align__(16) uint32_t pair16[1120];  // (f16 ts[i], f16 ts[i+1])
    __shared__ __align__(16) float wsq_sh[1056];     // 1e38 guard for s >= Sc
    __shared__ float ssq_sh[Lc];
    __shared__ float dsh[Lc];

    const int b    = blockIdx.x;
    const int tid  = threadIdx.x;
    const int w    = tid >> 5;
    const int lane = tid & 31;
    const int nrow = lane >> 2;
    const int kq   = lane & 3;

    // ---- stage ts + zero pad to 1152 ----
    {
        const float4* src = reinterpret_cast<const float4*>(ts + (size_t)b * Qc);
        float4* dst = reinterpret_cast<float4*>(ts_sh);
        dst[tid]       = src[tid];
        dst[128 + tid] = src[128 + tid];
        if (tid < 32) dst[256 + tid] = make_float4(0.f, 0.f, 0.f, 0.f);
    }
    __syncthreads();

    // ---- packed fp16 pair array ----
    #pragma unroll
    for (int i = tid; i < 1120; i += 128)
        pair16[i] = pack_f16x2(ts_sh[i], ts_sh[i + 1]);

    // ---- wsq[s] exact fp32 (incremental, 9 windows / thread) ----
    {
        const int sbase = tid * 9;
        if (sbase < 1056) {
            float ww = 0.f;
            #pragma unroll
            for (int k = 0; k < Kc; k++) {
                const float x = ts_sh[sbase + k];
                ww = fmaf(x, x, ww);
            }
            wsq_sh[sbase] = (sbase < Sc) ? ww : 1e38f;
            #pragma unroll
            for (int i = 1; i < 9; i++) {
                const int s = sbase + i;
                const float xo = ts_sh[s - 1], xn = ts_sh[s + 31];
                ww = ww - xo * xo + xn * xn;
                if (s < 1056) wsq_sh[s] = (s < Sc) ? ww : 1e38f;
            }
        }
    }

    // ---- ssq[l] exact fp32 ----
    if (tid < Lc) {
        float s = 0.f;
        #pragma unroll
        for (int k = 0; k < Kc; k++) {
            const float v = shp[tid * Kc + k];
            s = fmaf(v, v, s);
        }
        ssq_sh[tid] = s;
    }

    // ---- B fragments (fp16): warp covers n = w*16 .. w*16+15 ----
    uint32_t Bf[2][2][2];
    #pragma unroll
    for (int nt = 0; nt < 2; nt++)
        #pragma unroll
        for (int kc = 0; kc < 2; kc++)
            #pragma unroll
            for (int j = 0; j < 2; j++) {
                const int n = w * 16 + nt * 8 + nrow;
                const int k = 16 * kc + 8 * j + 2 * kq;
                Bf[nt][kc][j] = pack_f16x2(shp[n * Kc + k], shp[n * Kc + k + 1]);
            }
    __syncthreads();

    // ---- main loop: 66 m16 tiles, 6-slot pair ring, pipelined merge ----
    float mn00 = 3.4e38f, mn01 = 3.4e38f, mn02 = 3.4e38f, mn03 = 3.4e38f;
    float mn10 = 3.4e38f, mn11 = 3.4e38f, mn12 = 3.4e38f, mn13 = 3.4e38f;

    const int tb = nrow + 2 * kq;   // in [0,13]
    uint32_t rr[6];
    #pragma unroll
    for (int m = 0; m < 5; m++) rr[m] = pair16[tb + 8 * m];
    rr[5] = 0u;

    float dA0,dA1,dA2,dA3,dA4,dA5,dA6,dA7;
    float dB0,dB1,dB2,dB3,dB4,dB5,dB6,dB7;
    float wq0A, wq1A, wq0B, wq1B;

    #pragma unroll 1
    for (int it = 0; it < 11; it++) {
        const int t6 = it * 6;
        TILE_MMA(0, A, t6);
        TILE_MMA(2, B, t6 + 1);
        MERGE_S(A);
        TILE_MMA(4, A, t6 + 2);
        MERGE_S(B);
        TILE_MMA(0, B, t6 + 3);
        MERGE_S(A);
        TILE_MMA(2, A, t6 + 4);
        MERGE_S(B);
        TILE_MMA(4, B, t6 + 5);
        MERGE_S(A);
        MERGE_S(B);
    }

    // ---- reduce rows in-thread, then across row groups via shfl ----
    float m0 = fminf(mn00, mn02);
    float m1 = fminf(mn01, mn03);
    float m2 = fminf(mn10, mn12);
    float m3 = fminf(mn11, mn13);
    #pragma unroll
    for (int off = 4; off < 32; off <<= 1) {
        m0 = fminf(m0, __shfl_xor_sync(0xffffffffu, m0, off));
        m1 = fminf(m1, __shfl_xor_sync(0xffffffffu, m1, off));
        m2 = fminf(m2, __shfl_xor_sync(0xffffffffu, m2, off));
        m3 = fminf(m3, __shfl_xor_sync(0xffffffffu, m3, off));
    }
    if (nrow == 0) {
        const int n0 = w * 16 + 2 * kq;
        dsh[n0]     = (m0 + ssq_sh[n0])     * (1.0f / Kc);
        dsh[n0 + 1] = (m1 + ssq_sh[n0 + 1]) * (1.0f / Kc);
        dsh[n0 + 8] = (m2 + ssq_sh[n0 + 8]) * (1.0f / Kc);
        dsh[n0 + 9] = (m3 + ssq_sh[n0 + 9]) * (1.0f / Kc);
    }
    __syncthreads();

    // ---- FC epilogue ----
    if (tid < 2 * 32) {
        const int c = tid >> 5;
        const int l = tid & 31;
        float p = dsh[l] * fc_w[c * Lc + l]
                + dsh[l + 32] * fc_w[c * Lc + l + 32];
        #pragma unroll
        for (int off = 16; off > 0; off >>= 1)
            p += __shfl_down_sync(0xffffffffu, p, off);
        if (l == 0) out[b * 2 + c] = p + fc_b[c];
    }
}

extern "C" void kernel_launch(void* const* d_in, const int* in_sizes, int n_in,
                              void* d_out, int out_size)
{
    (void)in_sizes; (void)n_in; (void)out_size;
    const float* ts   = (const float*)d_in[0];
    const float* shp  = (const float*)d_in[1];
    const float* fc_w = (const float*)d_in[2];
    const float* fc_b = (const float*)d_in[3];
    float* out        = (float*)d_out;
    shapelet_hmma<<<Bc, 128>>>(ts, shp, fc_w, fc_b, out);
}

// round 11
// speedup vs baseline: 2.8188x; 1.0617x over previous
#include <cuda_runtime.h>
#include <cuda_fp16.h>
#include <cstdint>

// ---------------------------------------------------------------------------
// ShapletLearner via single-pass fp16 mma.sync m16n8k16.
// R11: B pre-scaled by -2 (exact in fp16) and wsq folded into the HMMA C
// operand -> D = wsq - 2*cross directly; merge is 8 FMNMX/tile (no FFMAs).
// wq values prefetched two tiles ahead so the C operand is never LDS-stalled.
// A/B accumulator sets with deferred merge (R9/R10 pipeline) retained.
// ---------------------------------------------------------------------------

constexpr int Bc = 2048;
constexpr int Qc = 1024;
constexpr int Kc = 32;
constexpr int Lc = 64;
constexpr int Sc = Qc - Kc + 1;   // 993

// D = A*B + {c0,c0,c1,c1}   (wsq folded in; starts the chain)
#define MMAC(d0,d1,d2,d3, a0,a1,a2,a3, b0,b1, c0,c1) \
    asm("mma.sync.aligned.m16n8k16.row.col.f32.f16.f16.f32 " \
        "{%0,%1,%2,%3}, {%4,%5,%6,%7}, {%8,%9}, {%10,%11,%12,%13};" \
        : "=f"(d0), "=f"(d1), "=f"(d2), "=f"(d3) \
        : "r"(a0), "r"(a1), "r"(a2), "r"(a3), "r"(b0), "r"(b1), \
          "f"(c0), "f"(c0), "f"(c1), "f"(c1))

// D += A*B
#define MMAB(d0,d1,d2,d3, a0,a1,a2,a3, b0,b1) \
    asm("mma.sync.aligned.m16n8k16.row.col.f32.f16.f16.f32 " \
        "{%0,%1,%2,%3}, {%4,%5,%6,%7}, {%8,%9}, {%0,%1,%2,%3};" \
        : "+f"(d0), "+f"(d1), "+f"(d2), "+f"(d3) \
        : "r"(a0), "r"(a1), "r"(a2), "r"(a3), "r"(b0), "r"(b1))

// One m16 tile into accumulator set S. Uses wq0S/wq1S (prefetched 2 tiles
// ago), then prefetches wq for tile TT+2 and ring pairs for tile TT+1.
#define TILE_MMA(O, S, TT) do { \
    enum { I0 = (O) % 6, I1 = ((O) + 1) % 6, I2 = ((O) + 2) % 6, \
           I3 = ((O) + 3) % 6, I4 = ((O) + 4) % 6, S5 = ((O) + 5) % 6 }; \
    const int s0_ = (TT) << 4; \
    MMAC(d##S##0,d##S##1,d##S##2,d##S##3, rr[I0],rr[I1],rr[I1],rr[I2], \
         Bf[0][0][0],Bf[0][0][1], wq0##S, wq1##S); \
    MMAC(d##S##4,d##S##5,d##S##6,d##S##7, rr[I0],rr[I1],rr[I1],rr[I2], \
         Bf[1][0][0],Bf[1][0][1], wq0##S, wq1##S); \
    MMAB(d##S##0,d##S##1,d##S##2,d##S##3, rr[I2],rr[I3],rr[I3],rr[I4], \
         Bf[0][1][0],Bf[0][1][1]); \
    MMAB(d##S##4,d##S##5,d##S##6,d##S##7, rr[I2],rr[I3],rr[I3],rr[I4], \
         Bf[1][1][0],Bf[1][1][1]); \
    wq0##S = wsq_sh[s0_ + 32 + nrow]; \
    wq1##S = wsq_sh[s0_ + 32 + nrow + 8]; \
    { const int gi_ = s0_ + tb; \
      rr[S5] = pair16[gi_ + 40]; \
      rr[I0] = pair16[gi_ + 48]; } \
} while (0)

// merge set S (raw dist values) into running mins — 8 FMNMX
#define MERGE_S(S) do { \
    mn00 = fminf(mn00, d##S##0);  mn01 = fminf(mn01, d##S##1); \
    mn02 = fminf(mn02, d##S##2);  mn03 = fminf(mn03, d##S##3); \
    mn10 = fminf(mn10, d##S##4);  mn11 = fminf(mn11, d##S##5); \
    mn12 = fminf(mn12, d##S##6);  mn13 = fminf(mn13, d##S##7); \
} while (0)

static __device__ __forceinline__ uint32_t pack_f16x2(float lo, float hi) {
    uint32_t r;
    asm("cvt.rn.f16x2.f32 %0, %1, %2;" : "=r"(r) : "f"(hi), "f"(lo));
    return r;
}

__global__ __launch_bounds__(128) void shapelet_hmma(
    const float* __restrict__ ts,        // [B, Q]
    const float* __restrict__ shp,       // [L, K]
    const float* __restrict__ fc_w,      // [2, L]
    const float* __restrict__ fc_b,      // [2]
    float* __restrict__ out)             // [B, 2]
{
    __shared__ __align__(16) float    ts_sh[1152];   // fp32, zero-padded
    __shared__ __align__(16) uint32_t pair16[1120];  // (f16 ts[i], f16 ts[i+1])
    __shared__ __align__(16) float wsq_sh[1088];     // 1e38 guard for s >= Sc
    __shared__ float ssq_sh[Lc];
    __shared__ float dsh[Lc];

    const int b    = blockIdx.x;
    const int tid  = threadIdx.x;
    const int w    = tid >> 5;
    const int lane = tid & 31;
    const int nrow = lane >> 2;
    const int kq   = lane & 3;

    // ---- stage ts + zero pad to 1152 ----
    {
        const float4* src = reinterpret_cast<const float4*>(ts + (size_t)b * Qc);
        float4* dst = reinterpret_cast<float4*>(ts_sh);
        dst[tid]       = src[tid];
        dst[128 + tid] = src[128 + tid];
        if (tid < 32) dst[256 + tid] = make_float4(0.f, 0.f, 0.f, 0.f);
    }
    __syncthreads();

    // ---- packed fp16 pair array ----
    #pragma unroll
    for (int i = tid; i < 1120; i += 128)
        pair16[i] = pack_f16x2(ts_sh[i], ts_sh[i + 1]);

    // ---- wsq[s] exact fp32 (incremental, 9 windows / thread) ----
    {
        const int sbase = tid * 9;
        if (sbase < 1088) {
            float ww = 0.f;
            #pragma unroll
            for (int k = 0; k < Kc; k++) {
                const float x = ts_sh[sbase + k];
                ww = fmaf(x, x, ww);
            }
            wsq_sh[sbase] = (sbase < Sc) ? ww : 1e38f;
            #pragma unroll
            for (int i = 1; i < 9; i++) {
                const int s = sbase + i;
                const float xo = ts_sh[s - 1], xn = ts_sh[s + 31];
                ww = ww - xo * xo + xn * xn;
                if (s < 1088) wsq_sh[s] = (s < Sc) ? ww : 1e38f;
            }
        }
    }

    // ---- ssq[l] exact fp32 ----
    if (tid < Lc) {
        float s = 0.f;
        #pragma unroll
        for (int k = 0; k < Kc; k++) {
            const float v = shp[tid * Kc + k];
            s = fmaf(v, v, s);
        }
        ssq_sh[tid] = s;
    }

    // ---- B fragments (fp16, pre-scaled by -2): n = w*16 .. w*16+15 ----
    uint32_t Bf[2][2][2];
    #pragma unroll
    for (int nt = 0; nt < 2; nt++)
        #pragma unroll
        for (int kc = 0; kc < 2; kc++)
            #pragma unroll
            for (int j = 0; j < 2; j++) {
                const int n = w * 16 + nt * 8 + nrow;
                const int k = 16 * kc + 8 * j + 2 * kq;
                Bf[nt][kc][j] = pack_f16x2(-2.0f * shp[n * Kc + k],
                                           -2.0f * shp[n * Kc + k + 1]);
            }
    __syncthreads();

    // ---- main loop: 66 m16 tiles, 6-slot pair ring, pipelined merge ----
    float mn00 = 3.4e38f, mn01 = 3.4e38f, mn02 = 3.4e38f, mn03 = 3.4e38f;
    float mn10 = 3.4e38f, mn11 = 3.4e38f, mn12 = 3.4e38f, mn13 = 3.4e38f;

    const int tb = nrow + 2 * kq;   // in [0,13]
    uint32_t rr[6];
    #pragma unroll
    for (int m = 0; m < 5; m++) rr[m] = pair16[tb + 8 * m];
    rr[5] = 0u;

    float dA0,dA1,dA2,dA3,dA4,dA5,dA6,dA7;
    float dB0,dB1,dB2,dB3,dB4,dB5,dB6,dB7;

    // wq prologue: set A serves tile 0, set B serves tile 1
    float wq0A = wsq_sh[nrow],      wq1A = wsq_sh[nrow + 8];
    float wq0B = wsq_sh[16 + nrow], wq1B = wsq_sh[16 + nrow + 8];

    #pragma unroll 1
    for (int it = 0; it < 11; it++) {
        const int t6 = it * 6;
        TILE_MMA(0, A, t6);
        TILE_MMA(2, B, t6 + 1);
        MERGE_S(A);
        TILE_MMA(4, A, t6 + 2);
        MERGE_S(B);
        TILE_MMA(0, B, t6 + 3);
        MERGE_S(A);
        TILE_MMA(2, A, t6 + 4);
        MERGE_S(B);
        TILE_MMA(4, B, t6 + 5);
        MERGE_S(A);
        MERGE_S(B);
    }

    // ---- reduce rows in-thread, then across row groups via shfl ----
    float m0 = fminf(mn00, mn02);
    float m1 = fminf(mn01, mn03);
    float m2 = fminf(mn10, mn12);
    float m3 = fminf(mn11, mn13);
    #pragma unroll
    for (int off = 4; off < 32; off <<= 1) {
        m0 = fminf(m0, __shfl_xor_sync(0xffffffffu, m0, off));
        m1 = fminf(m1, __shfl_xor_sync(0xffffffffu, m1, off));
        m2 = fminf(m2, __shfl_xor_sync(0xffffffffu, m2, off));
        m3 = fminf(m3, __shfl_xor_sync(0xffffffffu, m3, off));
    }
    if (nrow == 0) {
        const int n0 = w * 16 + 2 * kq;
        dsh[n0]     = (m0 + ssq_sh[n0])     * (1.0f / Kc);
        dsh[n0 + 1] = (m1 + ssq_sh[n0 + 1]) * (1.0f / Kc);
        dsh[n0 + 8] = (m2 + ssq_sh[n0 + 8]) * (1.0f / Kc);
        dsh[n0 + 9] = (m3 + ssq_sh[n0 + 9]) * (1.0f / Kc);
    }
    __syncthreads();

    // ---- FC epilogue ----
    if (tid < 2 * 32) {
        const int c = tid >> 5;
        const int l = tid & 31;
        float p = dsh[l] * fc_w[c * Lc + l]
                + dsh[l + 32] * fc_w[c * Lc + l + 32];
        #pragma unroll
        for (int off = 16; off > 0; off >>= 1)
            p += __shfl_down_sync(0xffffffffu, p, off);
        if (l == 0) out[b * 2 + c] = p + fc_b[c];
    }
}

extern "C" void kernel_launch(void* const* d_in, const int* in_sizes, int n_in,
                              void* d_out, int out_size)
{
    (void)in_sizes; (void)n_in; (void)out_size;
    const float* ts   = (const float*)d_in[0];
    const float* shp  = (const float*)d_in[1];
    const float* fc_w = (const float*)d_in[2];
    const float* fc_b = (const float*)d_in[3];
    float* out        = (float*)d_out;
    shapelet_hmma<<<Bc, 128>>>(ts, shp, fc_w, fc_b, out);
}